// round 13
// baseline (speedup 1.0000x reference)
#include <cuda_runtime.h>
#include <cuda_fp16.h>
#include <math.h>
#include <stdint.h>

#define Bb 4
#define Nn 10000
#define Dd 128
#define DE 32
#define Ee 640000
#define NODES (Bb*Nn)            // 40000
#define NODES_PAD 40064          // 313 * 128
#define RSQRT_DH 0.17677669529663687f

// ---------------- scratch (device globals; zero-init, no allocation) ---------
__device__ float2 g_qka[NODES];          // {qa, ka} packed
__device__ float g_att_sum[NODES];
__device__ int   g_counts[NODES];
__device__ int   g_offsets[NODES + 1];
__device__ int   g_cursor[NODES];
__device__ int4  g_edge4[Ee];            // {dst_node, exp_bits, src_node, 0} src-sorted
__device__ __half g_eh[(size_t)Ee * DE]; // fp16 e_emb rows in src-sorted order (41 MB)
__device__ __half g_xh[NODES * Dd];      // fp16 copy of x (10 MB, L2-resident)
__device__ float g_Mx[NODES_PAD * Dd];   // Σ alpha * x[dst]   (atomic targets)
__device__ float g_Me[NODES_PAD * DE];   // Σ alpha * e_emb[e] (atomic targets)
__device__ float g_sA[NODES_PAD];        // Σ alpha            (atomic targets)
__device__ float g_wqa[Dd];
__device__ float g_wka[Dd];
__device__ float g_wewa[DE];
__device__ float g_bvev[Dd];             // bv + bev
__device__ float g_cc;                   // (bq+bk+bew)·Wa

// ---------------- helpers -----------------------------------------------------
__device__ __forceinline__ void cp16(void* dst, const void* src) {
    uint32_t d = (uint32_t)__cvta_generic_to_shared(dst);
    asm volatile("cp.async.cg.shared.global [%0], [%1], 16;" :: "r"(d), "l"(src));
}
#define CP_COMMIT() asm volatile("cp.async.commit_group;")
#define CP_WAIT(n)  asm volatile("cp.async.wait_group %0;" :: "n"(n))

__device__ __forceinline__ float4 h4tof4(uint2 r) {
    __half2* p = (__half2*)&r;
    float2 lo = __half22float2(p[0]);
    float2 hi = __half22float2(p[1]);
    return make_float4(lo.x, lo.y, hi.x, hi.y);
}

__device__ __forceinline__ uint32_t f2tf32(float f) {
    uint32_t u;
    asm("cvt.rna.tf32.f32 %0, %1;" : "=r"(u) : "f"(f));
    return u;
}

__device__ __forceinline__ void mma_tf32(float* d, const uint32_t* a,
                                         uint32_t b0, uint32_t b1) {
    asm volatile(
        "mma.sync.aligned.m16n8k8.row.col.f32.tf32.tf32.f32 "
        "{%0,%1,%2,%3},{%4,%5,%6,%7},{%8,%9},{%0,%1,%2,%3};"
        : "+f"(d[0]), "+f"(d[1]), "+f"(d[2]), "+f"(d[3])
        : "r"(a[0]), "r"(a[1]), "r"(a[2]), "r"(a[3]), "r"(b0), "r"(b1));
}

// ---------------- K0: fused zero (acc + moments) + prep ----------------------
#define ZERO_BLKS 157                   // att_sum + counts
#define PREP_BLKS 16
#define MX_BLKS   5000                  // NODES*Dd/4/256
#define ME_BLKS   1250                  // NODES*DE/4/256
#define SA_BLKS   40                    // ceil(NODES/4/256)
__global__ void k_init(const float* __restrict__ Wq, const float* __restrict__ Wk,
                       const float* __restrict__ Wew,
                       const float* __restrict__ bq, const float* __restrict__ bk,
                       const float* __restrict__ bew, const float* __restrict__ Wa,
                       const float* __restrict__ bv, const float* __restrict__ bev) {
    int bid = blockIdx.x;
    if (bid < ZERO_BLKS) {
        int i = bid * 256 + threadIdx.x;
        if (i < NODES) { g_att_sum[i] = 0.f; g_counts[i] = 0; }
        return;
    }
    bid -= ZERO_BLKS;
    if (bid < PREP_BLKS) {
        int w    = (bid * 256 + threadIdx.x) >> 5;
        int lane = threadIdx.x & 31;
        if (w >= Dd) return;
        float a = 0.f, b = 0.f, c = 0.f, cc = 0.f;
        #pragma unroll
        for (int j = lane; j < Dd; j += 32) {
            float wa = Wa[j];
            a += Wq[w * Dd + j] * wa;
            b += Wk[w * Dd + j] * wa;
            if (w < DE) c += Wew[w * Dd + j] * wa;
            if (w == 0) cc += (bq[j] + bk[j] + bew[j]) * wa;
        }
        #pragma unroll
        for (int off = 16; off > 0; off >>= 1) {
            a  += __shfl_xor_sync(0xffffffffu, a, off);
            b  += __shfl_xor_sync(0xffffffffu, b, off);
            c  += __shfl_xor_sync(0xffffffffu, c, off);
            cc += __shfl_xor_sync(0xffffffffu, cc, off);
        }
        if (lane == 0) {
            g_wqa[w] = a;
            g_wka[w] = b;
            g_bvev[w] = bv[w] + bev[w];
            if (w < DE) g_wewa[w] = c;
            if (w == 0) g_cc = cc;
        }
        return;
    }
    bid -= PREP_BLKS;
    float4 z = make_float4(0.f, 0.f, 0.f, 0.f);
    if (bid < MX_BLKS) {
        ((float4*)g_Mx)[bid * 256 + threadIdx.x] = z;
        return;
    }
    bid -= MX_BLKS;
    if (bid < ME_BLKS) {
        ((float4*)g_Me)[bid * 256 + threadIdx.x] = z;
        return;
    }
    bid -= ME_BLKS;
    int i = bid * 256 + threadIdx.x;
    if (i < NODES / 4) ((float4*)g_sA)[i] = z;
}

// ---------------- K1: fused (x->fp16 + qa/ka) ∥ src histogram ----------------
#define FX_BLKS 5000   // NODES / 8 warps-per-block
__global__ void k_fxc(const float* __restrict__ x, const int* __restrict__ ei,
                      const int* __restrict__ bi) {
    if (blockIdx.x < FX_BLKS) {
        int warp = blockIdx.x * 8 + (threadIdx.x >> 5);
        int lane = threadIdx.x & 31;
        float4 xv = *(const float4*)&x[(size_t)warp * Dd + lane * 4];
        __half2 h0 = __floats2half2_rn(xv.x, xv.y);
        __half2 h1 = __floats2half2_rn(xv.z, xv.w);
        uint2 packed;
        packed.x = *(uint32_t*)&h0;
        packed.y = *(uint32_t*)&h1;
        *(uint2*)&g_xh[(size_t)warp * Dd + lane * 4] = packed;
        float4 wq = *(const float4*)&g_wqa[lane * 4];
        float4 wk = *(const float4*)&g_wka[lane * 4];
        float a = xv.x * wq.x + xv.y * wq.y + xv.z * wq.z + xv.w * wq.w;
        float b = xv.x * wk.x + xv.y * wk.y + xv.z * wk.z + xv.w * wk.w;
        #pragma unroll
        for (int off = 16; off > 0; off >>= 1) {
            a += __shfl_xor_sync(0xffffffffu, a, off);
            b += __shfl_xor_sync(0xffffffffu, b, off);
        }
        if (lane == 0) g_qka[warp] = make_float2(a, b);
        return;
    }
    int q = (blockIdx.x - FX_BLKS) * 256 + threadIdx.x;   // quad index
    if (q >= Ee / 4) return;
    int4 s4 = ((const int4*)ei)[q];
    int4 b4 = ((const int4*)bi)[q];
    atomicAdd(&g_counts[b4.x * Nn + s4.x], 1);
    atomicAdd(&g_counts[b4.y * Nn + s4.y], 1);
    atomicAdd(&g_counts[b4.z * Nn + s4.z], 1);
    atomicAdd(&g_counts[b4.w * Nn + s4.w], 1);
}

// ---------------- K4: single-block exclusive scan of counts ------------------
#define SCAN_T 1024
#define SCAN_CH 40
__global__ void k_scan() {
    __shared__ int sh[SCAN_T];
    int t = threadIdx.x;
    int start = t * SCAN_CH;
    int end = min(start + SCAN_CH, NODES);
    int s = 0;
    for (int i = start; i < end; i++) s += g_counts[i];
    sh[t] = s;
    __syncthreads();
    for (int off = 1; off < SCAN_T; off <<= 1) {
        int v = (t >= off) ? sh[t - off] : 0;
        __syncthreads();
        sh[t] += v;
        __syncthreads();
    }
    int run = (t == 0) ? 0 : sh[t - 1];
    for (int i = start; i < end; i++) {
        g_offsets[i] = run;
        g_cursor[i] = run;
        run += g_counts[i];
    }
    if (t == SCAN_T - 1) g_offsets[NODES] = sh[SCAN_T - 1];
}

// ---------------- K5: edge pass — dot, exp, seg-sum, sorted record + fp16 row
// Phase A packs fp16 while computing the dot (registers reused by Phase C).
__global__ __launch_bounds__(256) void k_edge1(const int* __restrict__ ei,
                                               const float* __restrict__ e_emb,
                                               const int* __restrict__ bi) {
    __shared__ float ws4[DE];
    __shared__ float s_cc;
    __shared__ float sdot[8][32];
    int t = threadIdx.x;
    if (t < DE) ws4[t] = g_wewa[t];
    if (t == 0) s_cc = g_cc;
    __syncthreads();

    int wid  = t >> 5;
    int lane = t & 31;
    int base = (blockIdx.x * 8 + wid) * 32;      // 32 edges per warp

    int e_mine = base + lane;
    int src = ei[e_mine];
    int dst = ei[Ee + e_mine];
    int b   = bi[e_mine];

    int oct  = lane >> 3;
    int sub  = lane & 7;
    float w0 = ws4[sub * 4 + 0], w1 = ws4[sub * 4 + 1];
    float w2 = ws4[sub * 4 + 2], w3 = ws4[sub * 4 + 3];
    uint2 pk16[8];
    #pragma unroll
    for (int g = 0; g < 8; g++) {
        int e4 = base + g * 4 + oct;
        float4 v = *(const float4*)&e_emb[(size_t)e4 * DE + sub * 4];
        float d = v.x * w0 + v.y * w1 + v.z * w2 + v.w * w3;
        __half2 h0 = __floats2half2_rn(v.x, v.y);
        __half2 h1 = __floats2half2_rn(v.z, v.w);
        pk16[g].x = *(uint32_t*)&h0;
        pk16[g].y = *(uint32_t*)&h1;
        d += __shfl_xor_sync(0xffffffffu, d, 4);
        d += __shfl_xor_sync(0xffffffffu, d, 2);
        d += __shfl_xor_sync(0xffffffffu, d, 1);
        if (sub == 0) sdot[wid][g * 4 + oct] = d;
    }
    __syncwarp();

    float dot = sdot[wid][lane];
    int key  = b * Nn + src;
    int dstn = b * Nn + dst;
    float2 qs = g_qka[key];
    float2 kd = g_qka[dstn];
    float logit = (qs.x + kd.y + dot + s_cc) * RSQRT_DH;
    float ex = __expf(logit);
    atomicAdd(&g_att_sum[dstn], ex);
    int pos = atomicAdd(&g_cursor[key], 1);
    int4 rec;
    rec.x = dstn;
    rec.y = __float_as_int(ex);
    rec.z = key;
    rec.w = 0;
    g_edge4[pos] = rec;

    #pragma unroll
    for (int g = 0; g < 8; g++) {
        int j = g * 4 + oct;
        int pj = __shfl_sync(0xffffffffu, pos, j);
        *(uint2*)&g_eh[(size_t)pj * DE + sub * 4] = pk16[g];
    }
}

// ---------------- K6: edge-centric segmented gather --------------------------
// One warp per 32 consecutive src-sorted edges; 4 independent 8-wide batches;
// segment flushes via RED atomics (moments zeroed in k_init).
#define GW (Ee / 32)   // 20000 warps
__global__ __launch_bounds__(128) void k_gather() {
    int w = blockIdx.x * 4 + (threadIdx.x >> 5);
    int lane = threadIdx.x & 31;
    if (w >= GW) return;
    int base = w * 32;

    float4 accx = make_float4(0.f, 0.f, 0.f, 0.f);
    float acce = 0.f, accA = 0.f;
    int cur = g_edge4[base].z;

    #pragma unroll
    for (int bb = 0; bb < 4; bb++) {
        int i = base + bb * 8;
        int4 m[8];
        #pragma unroll
        for (int k = 0; k < 8; k++) m[k] = g_edge4[i + k];
        uint2 r[8];
        #pragma unroll
        for (int k = 0; k < 8; k++)
            r[k] = *(const uint2*)&g_xh[(size_t)m[k].x * Dd + lane * 4];
        float h[8];
        #pragma unroll
        for (int k = 0; k < 8; k++)
            h[k] = __half2float(g_eh[(size_t)(i + k) * DE + lane]);
        float sm[8];
        #pragma unroll
        for (int k = 0; k < 8; k++) sm[k] = g_att_sum[m[k].x];
        #pragma unroll
        for (int k = 0; k < 8; k++) {
            if (m[k].z != cur) {        // warp-uniform segment boundary
                atomicAdd(&g_Mx[(size_t)cur * Dd + lane * 4 + 0], accx.x);
                atomicAdd(&g_Mx[(size_t)cur * Dd + lane * 4 + 1], accx.y);
                atomicAdd(&g_Mx[(size_t)cur * Dd + lane * 4 + 2], accx.z);
                atomicAdd(&g_Mx[(size_t)cur * Dd + lane * 4 + 3], accx.w);
                atomicAdd(&g_Me[(size_t)cur * DE + lane], acce);
                if (lane == 0) atomicAdd(&g_sA[cur], accA);
                cur = m[k].z;
                accx = make_float4(0.f, 0.f, 0.f, 0.f);
                acce = 0.f; accA = 0.f;
            }
            float a = __fdividef(__int_as_float(m[k].y), sm[k] + 1e-9f);
            float4 v = h4tof4(r[k]);
            accx.x += a * v.x; accx.y += a * v.y;
            accx.z += a * v.z; accx.w += a * v.w;
            acce += a * h[k];
            accA += a;
        }
    }
    atomicAdd(&g_Mx[(size_t)cur * Dd + lane * 4 + 0], accx.x);
    atomicAdd(&g_Mx[(size_t)cur * Dd + lane * 4 + 1], accx.y);
    atomicAdd(&g_Mx[(size_t)cur * Dd + lane * 4 + 2], accx.z);
    atomicAdd(&g_Mx[(size_t)cur * Dd + lane * 4 + 3], accx.w);
    atomicAdd(&g_Me[(size_t)cur * DE + lane], acce);
    if (lane == 0) atomicAdd(&g_sA[cur], accA);
}

// ---------------- K7: tf32 tensor-core epilogue GEMM -------------------------
#define OB_M 128
#define OB_K 16
#define NTILES 10
#define ASTR 20
#define BSTR 136
__global__ __launch_bounds__(256) void k_out(const float* __restrict__ Wv,
                                             const float* __restrict__ Wev,
                                             float* __restrict__ out) {
    __shared__ float As[2][OB_M * ASTR];
    __shared__ float Bs[2][OB_K * BSTR];
    __shared__ float sA_sh[OB_M];
    __shared__ float bb_sh[Dd];

    int t  = threadIdx.x;
    int m0 = blockIdx.x * OB_M;
    if (t < OB_M) {
        sA_sh[t] = g_sA[m0 + t];
        bb_sh[t] = g_bvev[t];
    }

    auto issue = [&](int stage, int tile) {
        #pragma unroll
        for (int it = 0; it < 2; it++) {
            int q = t + it * 256;
            int m = q >> 2, kq = q & 3;
            const float* srcA = (tile < 8)
                ? &g_Mx[(size_t)(m0 + m) * Dd + tile * OB_K + kq * 4]
                : &g_Me[(size_t)(m0 + m) * DE + (tile - 8) * OB_K + kq * 4];
            cp16(&As[stage][m * ASTR + kq * 4], srcA);
            int k = q >> 5, c4 = q & 31;
            const float* srcB = (tile < 8)
                ? &Wv[(size_t)(tile * OB_K + k) * Dd + c4 * 4]
                : &Wev[(size_t)((tile - 8) * OB_K + k) * Dd + c4 * 4];
            cp16(&Bs[stage][k * BSTR + c4 * 4], srcB);
        }
    };

    issue(0, 0);
    CP_COMMIT();

    int wid  = t >> 5;
    int lane = t & 31;
    int warp_m = wid >> 1;
    int warp_n = wid & 1;
    int gID = lane >> 2, tig = lane & 3;

    float d[2][8][4];
    #pragma unroll
    for (int mi = 0; mi < 2; mi++)
        #pragma unroll
        for (int ni = 0; ni < 8; ni++)
            #pragma unroll
            for (int k = 0; k < 4; k++) d[mi][ni][k] = 0.f;

    for (int tile = 0; tile < NTILES; tile++) {
        int cur = tile & 1, nxt = cur ^ 1;
        if (tile + 1 < NTILES) {
            issue(nxt, tile + 1);
            CP_COMMIT();
            CP_WAIT(1);
        } else {
            CP_WAIT(0);
        }
        __syncthreads();
        #pragma unroll
        for (int ks = 0; ks < OB_K; ks += 8) {
            uint32_t a[2][4];
            #pragma unroll
            for (int mi = 0; mi < 2; mi++) {
                int r0 = warp_m * 32 + mi * 16 + gID;
                a[mi][0] = f2tf32(As[cur][(r0)     * ASTR + ks + tig]);
                a[mi][1] = f2tf32(As[cur][(r0 + 8) * ASTR + ks + tig]);
                a[mi][2] = f2tf32(As[cur][(r0)     * ASTR + ks + tig + 4]);
                a[mi][3] = f2tf32(As[cur][(r0 + 8) * ASTR + ks + tig + 4]);
            }
            #pragma unroll
            for (int ni = 0; ni < 8; ni++) {
                int cn = warp_n * 64 + ni * 8 + gID;
                uint32_t b0 = f2tf32(Bs[cur][(ks + tig)     * BSTR + cn]);
                uint32_t b1 = f2tf32(Bs[cur][(ks + tig + 4) * BSTR + cn]);
                mma_tf32(d[0][ni], a[0], b0, b1);
                mma_tf32(d[1][ni], a[1], b0, b1);
            }
        }
        __syncthreads();
    }

    #pragma unroll
    for (int mi = 0; mi < 2; mi++) {
        int rl = warp_m * 32 + mi * 16 + gID;
        int rh = rl + 8;
        int r_lo = m0 + rl, r_hi = m0 + rh;
        float sa_lo = sA_sh[rl], sa_hi = sA_sh[rh];
        #pragma unroll
        for (int ni = 0; ni < 8; ni++) {
            int c = warp_n * 64 + ni * 8 + tig * 2;
            float b0 = bb_sh[c], b1 = bb_sh[c + 1];
            if (r_lo < NODES) {
                float2 o = make_float2(d[mi][ni][0] + sa_lo * b0,
                                       d[mi][ni][1] + sa_lo * b1);
                *(float2*)&out[(size_t)r_lo * Dd + c] = o;
            }
            if (r_hi < NODES) {
                float2 o = make_float2(d[mi][ni][2] + sa_hi * b0,
                                       d[mi][ni][3] + sa_hi * b1);
                *(float2*)&out[(size_t)r_hi * Dd + c] = o;
            }
        }
    }
}

// ---------------- launch ------------------------------------------------------
extern "C" void kernel_launch(void* const* d_in, const int* in_sizes, int n_in,
                              void* d_out, int out_size) {
    const float* x     = (const float*)d_in[0];
    const int*   ei    = (const int*)  d_in[1];
    const float* e_emb = (const float*)d_in[2];
    const int*   bi    = (const int*)  d_in[3];
    const float* Wq    = (const float*)d_in[4];
    const float* bq    = (const float*)d_in[5];
    const float* Wk    = (const float*)d_in[6];
    const float* bk    = (const float*)d_in[7];
    const float* Wv    = (const float*)d_in[8];
    const float* bv    = (const float*)d_in[9];
    const float* Wew   = (const float*)d_in[10];
    const float* bew   = (const float*)d_in[11];
    const float* Wev   = (const float*)d_in[12];
    const float* bev   = (const float*)d_in[13];
    const float* Wa    = (const float*)d_in[14];
    float* out = (float*)d_out;

    k_init<<<ZERO_BLKS + PREP_BLKS + MX_BLKS + ME_BLKS + SA_BLKS, 256>>>(
        Wq, Wk, Wew, bq, bk, bew, Wa, bv, bev);
    k_fxc<<<FX_BLKS + (Ee / 4 + 255) / 256, 256>>>(x, ei, bi);
    k_scan<<<1, SCAN_T>>>();
    k_edge1<<<Ee / 256, 256>>>(ei, e_emb, bi);
    k_gather<<<(GW + 3) / 4, 128>>>();
    k_out<<<NODES_PAD / OB_M, 256>>>(Wv, Wev, out);
}

// round 14
// speedup vs baseline: 1.3893x; 1.3893x over previous
#include <cuda_runtime.h>
#include <cuda_fp16.h>
#include <math.h>
#include <stdint.h>

#define Bb 4
#define Nn 10000
#define Dd 128
#define DE 32
#define Ee 640000
#define NODES (Bb*Nn)            // 40000
#define NODES_PAD 40064          // 313 * 128
#define RSQRT_DH 0.17677669529663687f

// ---------------- scratch (device globals; zero-init, no allocation) ---------
__device__ float2 g_qka[NODES];          // {qa, ka} packed
__device__ float g_att_sum[NODES];
__device__ __align__(16) int g_counts[NODES];
__device__ __align__(16) int g_offsets[NODES + 16];
__device__ __align__(16) int g_cursor[NODES + 16];
__device__ int2  g_edge2[Ee];            // {dst_node, exp->alpha bits} src-sorted
__device__ __half g_eh[(size_t)Ee * DE]; // fp16 e_emb rows in src-sorted order
__device__ __half g_xh[NODES * Dd];      // fp16 copy of x
__device__ float g_Mx[NODES_PAD * Dd];   // Σ alpha * x[dst]
__device__ float g_Me[NODES_PAD * DE];   // Σ alpha * e_emb[e]
__device__ float g_sA[NODES_PAD];        // Σ alpha
__device__ float g_wqa[Dd];
__device__ float g_wka[Dd];
__device__ float g_wewa[DE];
__device__ float g_bvev[Dd];             // bv + bev
__device__ float g_cc;                   // (bq+bk+bew)·Wa

// ---------------- helpers -----------------------------------------------------
__device__ __forceinline__ void cp16(void* dst, const void* src) {
    uint32_t d = (uint32_t)__cvta_generic_to_shared(dst);
    asm volatile("cp.async.cg.shared.global [%0], [%1], 16;" :: "r"(d), "l"(src));
}
#define CP_COMMIT() asm volatile("cp.async.commit_group;")
#define CP_WAIT(n)  asm volatile("cp.async.wait_group %0;" :: "n"(n))

__device__ __forceinline__ float4 h4tof4(uint2 r) {
    __half2* p = (__half2*)&r;
    float2 lo = __half22float2(p[0]);
    float2 hi = __half22float2(p[1]);
    return make_float4(lo.x, lo.y, hi.x, hi.y);
}

__device__ __forceinline__ uint32_t f2tf32(float f) {
    uint32_t u;
    asm("cvt.rna.tf32.f32 %0, %1;" : "=r"(u) : "f"(f));
    return u;
}

__device__ __forceinline__ void mma_tf32(float* d, const uint32_t* a,
                                         uint32_t b0, uint32_t b1) {
    asm volatile(
        "mma.sync.aligned.m16n8k8.row.col.f32.tf32.tf32.f32 "
        "{%0,%1,%2,%3},{%4,%5,%6,%7},{%8,%9},{%0,%1,%2,%3};"
        : "+f"(d[0]), "+f"(d[1]), "+f"(d[2]), "+f"(d[3])
        : "r"(a[0]), "r"(a[1]), "r"(a[2]), "r"(a[3]), "r"(b0), "r"(b1));
}

// ---------------- K1: zero accumulators --------------------------------------
__global__ void k_zero() {
    int i = blockIdx.x * blockDim.x + threadIdx.x;
    if (i < NODES) { g_att_sum[i] = 0.f; g_counts[i] = 0; }
}

// ---------------- K2: weight folding (warp per output row) -------------------
__global__ void k_prep(const float* __restrict__ Wq, const float* __restrict__ Wk,
                       const float* __restrict__ Wew,
                       const float* __restrict__ bq, const float* __restrict__ bk,
                       const float* __restrict__ bew, const float* __restrict__ Wa,
                       const float* __restrict__ bv, const float* __restrict__ bev) {
    int w    = (blockIdx.x * blockDim.x + threadIdx.x) >> 5;
    int lane = threadIdx.x & 31;
    if (w >= Dd) return;
    float a = 0.f, b = 0.f, c = 0.f, cc = 0.f;
    #pragma unroll
    for (int j = lane; j < Dd; j += 32) {
        float wa = Wa[j];
        a += Wq[w * Dd + j] * wa;
        b += Wk[w * Dd + j] * wa;
        if (w < DE) c += Wew[w * Dd + j] * wa;
        if (w == 0) cc += (bq[j] + bk[j] + bew[j]) * wa;
    }
    #pragma unroll
    for (int off = 16; off > 0; off >>= 1) {
        a  += __shfl_xor_sync(0xffffffffu, a, off);
        b  += __shfl_xor_sync(0xffffffffu, b, off);
        c  += __shfl_xor_sync(0xffffffffu, c, off);
        cc += __shfl_xor_sync(0xffffffffu, cc, off);
    }
    if (lane == 0) {
        g_wqa[w] = a;
        g_wka[w] = b;
        g_bvev[w] = bv[w] + bev[w];
        if (w < DE) g_wewa[w] = c;
        if (w == 0) g_cc = cc;
    }
}

// ---------------- K3: fused (x->fp16 + qa/ka) ∥ src histogram ----------------
#define FX_BLKS 5000
__global__ void k_fxc(const float* __restrict__ x, const int* __restrict__ ei,
                      const int* __restrict__ bi) {
    if (blockIdx.x < FX_BLKS) {
        int warp = blockIdx.x * 8 + (threadIdx.x >> 5);
        int lane = threadIdx.x & 31;
        float4 xv = *(const float4*)&x[(size_t)warp * Dd + lane * 4];
        __half2 h0 = __floats2half2_rn(xv.x, xv.y);
        __half2 h1 = __floats2half2_rn(xv.z, xv.w);
        uint2 packed;
        packed.x = *(uint32_t*)&h0;
        packed.y = *(uint32_t*)&h1;
        *(uint2*)&g_xh[(size_t)warp * Dd + lane * 4] = packed;
        float4 wq = *(const float4*)&g_wqa[lane * 4];
        float4 wk = *(const float4*)&g_wka[lane * 4];
        float a = xv.x * wq.x + xv.y * wq.y + xv.z * wq.z + xv.w * wq.w;
        float b = xv.x * wk.x + xv.y * wk.y + xv.z * wk.z + xv.w * wk.w;
        #pragma unroll
        for (int off = 16; off > 0; off >>= 1) {
            a += __shfl_xor_sync(0xffffffffu, a, off);
            b += __shfl_xor_sync(0xffffffffu, b, off);
        }
        if (lane == 0) g_qka[warp] = make_float2(a, b);
        return;
    }
    int q = (blockIdx.x - FX_BLKS) * 256 + threadIdx.x;
    if (q >= Ee / 4) return;
    int4 s4 = ((const int4*)ei)[q];
    int4 b4 = ((const int4*)bi)[q];
    atomicAdd(&g_counts[b4.x * Nn + s4.x], 1);
    atomicAdd(&g_counts[b4.y * Nn + s4.y], 1);
    atomicAdd(&g_counts[b4.z * Nn + s4.z], 1);
    atomicAdd(&g_counts[b4.w * Nn + s4.w], 1);
}

// ---------------- K4: vectorized single-block exclusive scan -----------------
// 1000 active threads x 40 counts each; int4 loads (MLP 10) and int4 stores.
#define SCAN_T 1024
#define SCAN_CH 40
__global__ void k_scan() {
    __shared__ int sh[SCAN_T];
    int t = threadIdx.x;
    int4 c[10];
    int s = 0;
    if (t < 1000) {
        #pragma unroll
        for (int q = 0; q < 10; q++) {
            c[q] = ((const int4*)g_counts)[t * 10 + q];
            s += c[q].x + c[q].y + c[q].z + c[q].w;
        }
    }
    sh[t] = s;
    __syncthreads();
    for (int off = 1; off < SCAN_T; off <<= 1) {
        int v = (t >= off) ? sh[t - off] : 0;
        __syncthreads();
        sh[t] += v;
        __syncthreads();
    }
    if (t < 1000) {
        int run = (t == 0) ? 0 : sh[t - 1];
        #pragma unroll
        for (int q = 0; q < 10; q++) {
            int4 cv = c[q];
            int4 ov;
            ov.x = run;
            ov.y = ov.x + cv.x;
            ov.z = ov.y + cv.y;
            ov.w = ov.z + cv.z;
            run  = ov.w + cv.w;
            ((int4*)g_offsets)[t * 10 + q] = ov;
            ((int4*)g_cursor)[t * 10 + q]  = ov;
        }
    }
    if (t == SCAN_T - 1) g_offsets[NODES] = sh[SCAN_T - 1];
}

// ---------------- K5: edge pass — dot, exp, seg-sum, sorted record + fp16 row
__global__ __launch_bounds__(256) void k_edge1(const int* __restrict__ ei,
                                               const float* __restrict__ e_emb,
                                               const int* __restrict__ bi) {
    __shared__ float ws4[DE];
    __shared__ float s_cc;
    __shared__ float sdot[8][32];
    int t = threadIdx.x;
    if (t < DE) ws4[t] = g_wewa[t];
    if (t == 0) s_cc = g_cc;
    __syncthreads();

    int wid  = t >> 5;
    int lane = t & 31;
    int base = (blockIdx.x * 8 + wid) * 32;

    int e_mine = base + lane;
    int src = ei[e_mine];
    int dst = ei[Ee + e_mine];
    int b   = bi[e_mine];

    int oct  = lane >> 3;
    int sub  = lane & 7;
    float w0 = ws4[sub * 4 + 0], w1 = ws4[sub * 4 + 1];
    float w2 = ws4[sub * 4 + 2], w3 = ws4[sub * 4 + 3];
    uint2 pk16[8];
    #pragma unroll
    for (int g = 0; g < 8; g++) {
        int e4 = base + g * 4 + oct;
        float4 v = *(const float4*)&e_emb[(size_t)e4 * DE + sub * 4];
        float d = v.x * w0 + v.y * w1 + v.z * w2 + v.w * w3;
        __half2 h0 = __floats2half2_rn(v.x, v.y);
        __half2 h1 = __floats2half2_rn(v.z, v.w);
        pk16[g].x = *(uint32_t*)&h0;
        pk16[g].y = *(uint32_t*)&h1;
        d += __shfl_xor_sync(0xffffffffu, d, 4);
        d += __shfl_xor_sync(0xffffffffu, d, 2);
        d += __shfl_xor_sync(0xffffffffu, d, 1);
        if (sub == 0) sdot[wid][g * 4 + oct] = d;
    }
    __syncwarp();

    float dot = sdot[wid][lane];
    int key  = b * Nn + src;
    int dstn = b * Nn + dst;
    float2 qs = g_qka[key];
    float2 kd = g_qka[dstn];
    float logit = (qs.x + kd.y + dot + s_cc) * RSQRT_DH;
    float ex = __expf(logit);
    atomicAdd(&g_att_sum[dstn], ex);
    int pos = atomicAdd(&g_cursor[key], 1);
    g_edge2[pos] = make_int2(dstn, __float_as_int(ex));

    #pragma unroll
    for (int g = 0; g < 8; g++) {
        int j = g * 4 + oct;
        int pj = __shfl_sync(0xffffffffu, pos, j);
        *(uint2*)&g_eh[(size_t)pj * DE + sub * 4] = pk16[g];
    }
}

// ---------------- K6: fold alpha into records (exp -> exp/att_sum) -----------
__global__ void k_alpha() {
    int q = blockIdx.x * blockDim.x + threadIdx.x;   // record pair index
    if (q >= Ee / 2) return;
    int4 pr = ((const int4*)g_edge2)[q];             // {d0, x0, d1, x1}
    float a0 = __fdividef(__int_as_float(pr.y), g_att_sum[pr.x] + 1e-9f);
    float a1 = __fdividef(__int_as_float(pr.w), g_att_sum[pr.z] + 1e-9f);
    pr.y = __float_as_int(a0);
    pr.w = __float_as_int(a1);
    ((int4*)g_edge2)[q] = pr;
}

// ---------------- K7: gather moments, one warp per src node (8-wide) ---------
__global__ __launch_bounds__(128) void k_gather() {
    int s = blockIdx.x * 4 + (threadIdx.x >> 5);
    int lane = threadIdx.x & 31;
    if (s >= NODES) return;

    int start = g_offsets[s];
    int end   = g_offsets[s + 1];

    float4 accx = make_float4(0.f, 0.f, 0.f, 0.f);
    float acce = 0.f;
    float accA = 0.f;

    int i = start;
    for (; i + 8 <= end; i += 8) {
        int2 m[8];
        #pragma unroll
        for (int k = 0; k < 8; k++) m[k] = g_edge2[i + k];
        uint2 r[8];
        #pragma unroll
        for (int k = 0; k < 8; k++)
            r[k] = *(const uint2*)&g_xh[(size_t)m[k].x * Dd + lane * 4];
        float h[8];
        #pragma unroll
        for (int k = 0; k < 8; k++)
            h[k] = __half2float(g_eh[(size_t)(i + k) * DE + lane]);
        #pragma unroll
        for (int k = 0; k < 8; k++) {
            float a = __int_as_float(m[k].y);
            float4 v = h4tof4(r[k]);
            accx.x += a * v.x; accx.y += a * v.y;
            accx.z += a * v.z; accx.w += a * v.w;
            acce += a * h[k];
            accA += a;
        }
    }
    for (; i < end; i++) {
        int2 m = g_edge2[i];
        float h = __half2float(g_eh[(size_t)i * DE + lane]);
        uint2 r = *(const uint2*)&g_xh[(size_t)m.x * Dd + lane * 4];
        float a = __int_as_float(m.y);
        float4 v = h4tof4(r);
        accx.x += a * v.x; accx.y += a * v.y;
        accx.z += a * v.z; accx.w += a * v.w;
        acce += a * h;
        accA += a;
    }

    *(float4*)&g_Mx[(size_t)s * Dd + lane * 4] = accx;
    g_Me[(size_t)s * DE + lane] = acce;
    if (lane == 0) g_sA[s] = accA;
}

// ---------------- K8: tf32 tensor-core epilogue GEMM -------------------------
#define OB_M 128
#define OB_K 16
#define NTILES 10
#define ASTR 20
#define BSTR 136
__global__ __launch_bounds__(256) void k_out(const float* __restrict__ Wv,
                                             const float* __restrict__ Wev,
                                             float* __restrict__ out) {
    __shared__ float As[2][OB_M * ASTR];
    __shared__ float Bs[2][OB_K * BSTR];
    __shared__ float sA_sh[OB_M];
    __shared__ float bb_sh[Dd];

    int t  = threadIdx.x;
    int m0 = blockIdx.x * OB_M;
    if (t < OB_M) {
        sA_sh[t] = g_sA[m0 + t];
        bb_sh[t] = g_bvev[t];
    }

    auto issue = [&](int stage, int tile) {
        #pragma unroll
        for (int it = 0; it < 2; it++) {
            int q = t + it * 256;
            int m = q >> 2, kq = q & 3;
            const float* srcA = (tile < 8)
                ? &g_Mx[(size_t)(m0 + m) * Dd + tile * OB_K + kq * 4]
                : &g_Me[(size_t)(m0 + m) * DE + (tile - 8) * OB_K + kq * 4];
            cp16(&As[stage][m * ASTR + kq * 4], srcA);
            int k = q >> 5, c4 = q & 31;
            const float* srcB = (tile < 8)
                ? &Wv[(size_t)(tile * OB_K + k) * Dd + c4 * 4]
                : &Wev[(size_t)((tile - 8) * OB_K + k) * Dd + c4 * 4];
            cp16(&Bs[stage][k * BSTR + c4 * 4], srcB);
        }
    };

    issue(0, 0);
    CP_COMMIT();

    int wid  = t >> 5;
    int lane = t & 31;
    int warp_m = wid >> 1;
    int warp_n = wid & 1;
    int gID = lane >> 2, tig = lane & 3;

    float d[2][8][4];
    #pragma unroll
    for (int mi = 0; mi < 2; mi++)
        #pragma unroll
        for (int ni = 0; ni < 8; ni++)
            #pragma unroll
            for (int k = 0; k < 4; k++) d[mi][ni][k] = 0.f;

    for (int tile = 0; tile < NTILES; tile++) {
        int cur = tile & 1, nxt = cur ^ 1;
        if (tile + 1 < NTILES) {
            issue(nxt, tile + 1);
            CP_COMMIT();
            CP_WAIT(1);
        } else {
            CP_WAIT(0);
        }
        __syncthreads();
        #pragma unroll
        for (int ks = 0; ks < OB_K; ks += 8) {
            uint32_t a[2][4];
            #pragma unroll
            for (int mi = 0; mi < 2; mi++) {
                int r0 = warp_m * 32 + mi * 16 + gID;
                a[mi][0] = f2tf32(As[cur][(r0)     * ASTR + ks + tig]);
                a[mi][1] = f2tf32(As[cur][(r0 + 8) * ASTR + ks + tig]);
                a[mi][2] = f2tf32(As[cur][(r0)     * ASTR + ks + tig + 4]);
                a[mi][3] = f2tf32(As[cur][(r0 + 8) * ASTR + ks + tig + 4]);
            }
            #pragma unroll
            for (int ni = 0; ni < 8; ni++) {
                int cn = warp_n * 64 + ni * 8 + gID;
                uint32_t b0 = f2tf32(Bs[cur][(ks + tig)     * BSTR + cn]);
                uint32_t b1 = f2tf32(Bs[cur][(ks + tig + 4) * BSTR + cn]);
                mma_tf32(d[0][ni], a[0], b0, b1);
                mma_tf32(d[1][ni], a[1], b0, b1);
            }
        }
        __syncthreads();
    }

    #pragma unroll
    for (int mi = 0; mi < 2; mi++) {
        int rl = warp_m * 32 + mi * 16 + gID;
        int rh = rl + 8;
        int r_lo = m0 + rl, r_hi = m0 + rh;
        float sa_lo = sA_sh[rl], sa_hi = sA_sh[rh];
        #pragma unroll
        for (int ni = 0; ni < 8; ni++) {
            int c = warp_n * 64 + ni * 8 + tig * 2;
            float b0 = bb_sh[c], b1 = bb_sh[c + 1];
            if (r_lo < NODES) {
                float2 o = make_float2(d[mi][ni][0] + sa_lo * b0,
                                       d[mi][ni][1] + sa_lo * b1);
                *(float2*)&out[(size_t)r_lo * Dd + c] = o;
            }
            if (r_hi < NODES) {
                float2 o = make_float2(d[mi][ni][2] + sa_hi * b0,
                                       d[mi][ni][3] + sa_hi * b1);
                *(float2*)&out[(size_t)r_hi * Dd + c] = o;
            }
        }
    }
}

// ---------------- launch ------------------------------------------------------
extern "C" void kernel_launch(void* const* d_in, const int* in_sizes, int n_in,
                              void* d_out, int out_size) {
    const float* x     = (const float*)d_in[0];
    const int*   ei    = (const int*)  d_in[1];
    const float* e_emb = (const float*)d_in[2];
    const int*   bi    = (const int*)  d_in[3];
    const float* Wq    = (const float*)d_in[4];
    const float* bq    = (const float*)d_in[5];
    const float* Wk    = (const float*)d_in[6];
    const float* bk    = (const float*)d_in[7];
    const float* Wv    = (const float*)d_in[8];
    const float* bv    = (const float*)d_in[9];
    const float* Wew   = (const float*)d_in[10];
    const float* bew   = (const float*)d_in[11];
    const float* Wev   = (const float*)d_in[12];
    const float* bev   = (const float*)d_in[13];
    const float* Wa    = (const float*)d_in[14];
    float* out = (float*)d_out;

    k_zero<<<(NODES + 255) / 256, 256>>>();
    k_prep<<<16, 256>>>(Wq, Wk, Wew, bq, bk, bew, Wa, bv, bev);
    k_fxc<<<FX_BLKS + (Ee / 4 + 255) / 256, 256>>>(x, ei, bi);
    k_scan<<<1, SCAN_T>>>();                         // profiled slot 4
    k_edge1<<<Ee / 256, 256>>>(ei, e_emb, bi);
    k_alpha<<<(Ee / 2 + 255) / 256, 256>>>();
    k_gather<<<(NODES + 3) / 4, 128>>>();
    k_out<<<NODES_PAD / OB_M, 256>>>(Wv, Wev, out);
}

// round 16
// speedup vs baseline: 1.5333x; 1.1036x over previous
#include <cuda_runtime.h>
#include <cuda_fp16.h>
#include <math.h>
#include <stdint.h>

#define Bb 4
#define Nn 10000
#define Dd 128
#define DE 32
#define Ee 640000
#define NODES (Bb*Nn)            // 40000
#define NODES_PAD 40064          // 313 * 128
#define RSQRT_DH 0.17677669529663687f

// ---------------- scratch (device globals; zero-init, no allocation) ---------
__device__ float2 g_qka[NODES];          // {qa, ka} packed
__device__ float g_att_sum[NODES];
__device__ __align__(16) int g_counts[NODES];
__device__ __align__(16) int g_offsets[NODES + 16];
__device__ __align__(16) int g_cursor[NODES + 16];
__device__ int   g_bsum[40];
__device__ int2  g_edge2[Ee];            // {dst_node, exp->alpha bits} src-sorted
__device__ __half g_eh[(size_t)Ee * DE]; // fp16 e_emb rows in src-sorted order
__device__ __half g_xh[NODES * Dd];      // fp16 copy of x
__device__ float g_Mx[NODES_PAD * Dd];   // Σ alpha * x[dst]
__device__ float g_Me[NODES_PAD * DE];   // Σ alpha * e_emb[e]
__device__ float g_sA[NODES_PAD];        // Σ alpha
__device__ float g_wqa[Dd];
__device__ float g_wka[Dd];
__device__ float g_wewa[DE];
__device__ float g_bvev[Dd];             // bv + bev
__device__ float g_cc;                   // (bq+bk+bew)·Wa

// ---------------- helpers -----------------------------------------------------
__device__ __forceinline__ void cp16(void* dst, const void* src) {
    uint32_t d = (uint32_t)__cvta_generic_to_shared(dst);
    asm volatile("cp.async.cg.shared.global [%0], [%1], 16;" :: "r"(d), "l"(src));
}
#define CP_COMMIT() asm volatile("cp.async.commit_group;")
#define CP_WAIT(n)  asm volatile("cp.async.wait_group %0;" :: "n"(n))

__device__ __forceinline__ float4 h4tof4(uint2 r) {
    __half2* p = (__half2*)&r;
    float2 lo = __half22float2(p[0]);
    float2 hi = __half22float2(p[1]);
    return make_float4(lo.x, lo.y, hi.x, hi.y);
}

__device__ __forceinline__ uint32_t f2tf32(float f) {
    uint32_t u;
    asm("cvt.rna.tf32.f32 %0, %1;" : "=r"(u) : "f"(f));
    return u;
}

__device__ __forceinline__ void mma_tf32(float* d, const uint32_t* a,
                                         uint32_t b0, uint32_t b1) {
    asm volatile(
        "mma.sync.aligned.m16n8k8.row.col.f32.tf32.tf32.f32 "
        "{%0,%1,%2,%3},{%4,%5,%6,%7},{%8,%9},{%0,%1,%2,%3};"
        : "+f"(d[0]), "+f"(d[1]), "+f"(d[2]), "+f"(d[3])
        : "r"(a[0]), "r"(a[1]), "r"(a[2]), "r"(a[3]), "r"(b0), "r"(b1));
}

// ---------------- K0: fused zero + weight-fold prep --------------------------
#define ZERO_BLKS 157
__global__ void k_init(const float* __restrict__ Wq, const float* __restrict__ Wk,
                       const float* __restrict__ Wew,
                       const float* __restrict__ bq, const float* __restrict__ bk,
                       const float* __restrict__ bew, const float* __restrict__ Wa,
                       const float* __restrict__ bv, const float* __restrict__ bev) {
    if (blockIdx.x < ZERO_BLKS) {
        int i = blockIdx.x * 256 + threadIdx.x;
        if (i < NODES) { g_att_sum[i] = 0.f; g_counts[i] = 0; }
        return;
    }
    int w    = ((blockIdx.x - ZERO_BLKS) * 256 + threadIdx.x) >> 5;
    int lane = threadIdx.x & 31;
    if (w >= Dd) return;
    float a = 0.f, b = 0.f, c = 0.f, cc = 0.f;
    #pragma unroll
    for (int j = lane; j < Dd; j += 32) {
        float wa = Wa[j];
        a += Wq[w * Dd + j] * wa;
        b += Wk[w * Dd + j] * wa;
        if (w < DE) c += Wew[w * Dd + j] * wa;
        if (w == 0) cc += (bq[j] + bk[j] + bew[j]) * wa;
    }
    #pragma unroll
    for (int off = 16; off > 0; off >>= 1) {
        a  += __shfl_xor_sync(0xffffffffu, a, off);
        b  += __shfl_xor_sync(0xffffffffu, b, off);
        c  += __shfl_xor_sync(0xffffffffu, c, off);
        cc += __shfl_xor_sync(0xffffffffu, cc, off);
    }
    if (lane == 0) {
        g_wqa[w] = a;
        g_wka[w] = b;
        g_bvev[w] = bv[w] + bev[w];
        if (w < DE) g_wewa[w] = c;
        if (w == 0) g_cc = cc;
    }
}

// ---------------- K1: fused (x->fp16 + qa/ka) ∥ src histogram ----------------
#define FX_BLKS 5000
__global__ void k_fxc(const float* __restrict__ x, const int* __restrict__ ei,
                      const int* __restrict__ bi) {
    if (blockIdx.x < FX_BLKS) {
        int warp = blockIdx.x * 8 + (threadIdx.x >> 5);
        int lane = threadIdx.x & 31;
        float4 xv = *(const float4*)&x[(size_t)warp * Dd + lane * 4];
        __half2 h0 = __floats2half2_rn(xv.x, xv.y);
        __half2 h1 = __floats2half2_rn(xv.z, xv.w);
        uint2 packed;
        packed.x = *(uint32_t*)&h0;
        packed.y = *(uint32_t*)&h1;
        *(uint2*)&g_xh[(size_t)warp * Dd + lane * 4] = packed;
        float4 wq = *(const float4*)&g_wqa[lane * 4];
        float4 wk = *(const float4*)&g_wka[lane * 4];
        float a = xv.x * wq.x + xv.y * wq.y + xv.z * wq.z + xv.w * wq.w;
        float b = xv.x * wk.x + xv.y * wk.y + xv.z * wk.z + xv.w * wk.w;
        #pragma unroll
        for (int off = 16; off > 0; off >>= 1) {
            a += __shfl_xor_sync(0xffffffffu, a, off);
            b += __shfl_xor_sync(0xffffffffu, b, off);
        }
        if (lane == 0) g_qka[warp] = make_float2(a, b);
        return;
    }
    int q = (blockIdx.x - FX_BLKS) * 256 + threadIdx.x;
    if (q >= Ee / 4) return;
    int4 s4 = ((const int4*)ei)[q];
    int4 b4 = ((const int4*)bi)[q];
    atomicAdd(&g_counts[b4.x * Nn + s4.x], 1);
    atomicAdd(&g_counts[b4.y * Nn + s4.y], 1);
    atomicAdd(&g_counts[b4.z * Nn + s4.z], 1);
    atomicAdd(&g_counts[b4.w * Nn + s4.w], 1);
}

// ---------------- K2a: multi-block scan phase A (block-local) ----------------
#define SCAN_BLKS 40
__global__ void k_scanA() {
    __shared__ int wsum[8];
    int t = threadIdx.x, b = blockIdx.x;
    int idx4 = b * 256 + t;
    int4 c = make_int4(0, 0, 0, 0);
    if (idx4 < NODES / 4) c = ((const int4*)g_counts)[idx4];
    int tsum = c.x + c.y + c.z + c.w;
    int lane = t & 31, wid = t >> 5;
    int inc = tsum;
    #pragma unroll
    for (int off = 1; off < 32; off <<= 1) {
        int v = __shfl_up_sync(0xffffffffu, inc, off);
        if (lane >= off) inc += v;
    }
    if (lane == 31) wsum[wid] = inc;
    __syncthreads();
    int wpre = 0;
    #pragma unroll
    for (int k = 0; k < 8; k++) if (k < wid) wpre += wsum[k];
    int excl = wpre + inc - tsum;
    int4 o;
    o.x = excl;
    o.y = o.x + c.x;
    o.z = o.y + c.y;
    o.w = o.z + c.z;
    if (idx4 < NODES / 4) ((int4*)g_offsets)[idx4] = o;
    if (t == 255) g_bsum[b] = wpre + inc;   // block total
}

// ---------------- K2b: scan phase B (add block prefix, emit cursor) ----------
__global__ void k_scanB() {
    __shared__ int pre_s, tot_s;
    int t = threadIdx.x, b = blockIdx.x;
    if (t == 0) {
        int p = 0, tot = 0;
        #pragma unroll
        for (int k = 0; k < SCAN_BLKS; k++) {
            int v = g_bsum[k];
            if (k < b) p += v;
            tot += v;
        }
        pre_s = p; tot_s = tot;
    }
    __syncthreads();
    int pre = pre_s;
    int idx4 = b * 256 + t;
    if (idx4 < NODES / 4) {
        int4 o = ((const int4*)g_offsets)[idx4];
        o.x += pre; o.y += pre; o.z += pre; o.w += pre;
        ((int4*)g_offsets)[idx4] = o;
        ((int4*)g_cursor)[idx4]  = o;
    }
    if (b == 0 && t == 0) g_offsets[NODES] = tot_s;
}

// ---------------- K3: edge pass — dot, exp, seg-sum, sorted record + fp16 row
__global__ __launch_bounds__(256) void k_edge1(const int* __restrict__ ei,
                                               const float* __restrict__ e_emb,
                                               const int* __restrict__ bi) {
    __shared__ float ws4[DE];
    __shared__ float s_cc;
    __shared__ float sdot[8][32];
    int t = threadIdx.x;
    if (t < DE) ws4[t] = g_wewa[t];
    if (t == 0) s_cc = g_cc;
    __syncthreads();

    int wid  = t >> 5;
    int lane = t & 31;
    int base = (blockIdx.x * 8 + wid) * 32;

    int e_mine = base + lane;
    int src = ei[e_mine];
    int dst = ei[Ee + e_mine];
    int b   = bi[e_mine];

    int oct  = lane >> 3;
    int sub  = lane & 7;
    float w0 = ws4[sub * 4 + 0], w1 = ws4[sub * 4 + 1];
    float w2 = ws4[sub * 4 + 2], w3 = ws4[sub * 4 + 3];
    uint2 pk16[8];
    #pragma unroll
    for (int g = 0; g < 8; g++) {
        int e4 = base + g * 4 + oct;
        float4 v = *(const float4*)&e_emb[(size_t)e4 * DE + sub * 4];
        float d = v.x * w0 + v.y * w1 + v.z * w2 + v.w * w3;
        __half2 h0 = __floats2half2_rn(v.x, v.y);
        __half2 h1 = __floats2half2_rn(v.z, v.w);
        pk16[g].x = *(uint32_t*)&h0;
        pk16[g].y = *(uint32_t*)&h1;
        d += __shfl_xor_sync(0xffffffffu, d, 4);
        d += __shfl_xor_sync(0xffffffffu, d, 2);
        d += __shfl_xor_sync(0xffffffffu, d, 1);
        if (sub == 0) sdot[wid][g * 4 + oct] = d;
    }
    __syncwarp();

    float dot = sdot[wid][lane];
    int key  = b * Nn + src;
    int dstn = b * Nn + dst;
    float2 qs = g_qka[key];
    float2 kd = g_qka[dstn];
    float logit = (qs.x + kd.y + dot + s_cc) * RSQRT_DH;
    float ex = __expf(logit);
    atomicAdd(&g_att_sum[dstn], ex);
    int pos = atomicAdd(&g_cursor[key], 1);
    g_edge2[pos] = make_int2(dstn, __float_as_int(ex));

    #pragma unroll
    for (int g = 0; g < 8; g++) {
        int j = g * 4 + oct;
        int pj = __shfl_sync(0xffffffffu, pos, j);
        *(uint2*)&g_eh[(size_t)pj * DE + sub * 4] = pk16[g];
    }
}

// ---------------- K4: fold alpha into records (exp -> exp/att_sum) -----------
__global__ void k_alpha() {
    int q = blockIdx.x * blockDim.x + threadIdx.x;
    if (q >= Ee / 2) return;
    int4 pr = ((const int4*)g_edge2)[q];             // {d0, x0, d1, x1}
    float a0 = __fdividef(__int_as_float(pr.y), g_att_sum[pr.x] + 1e-9f);
    float a1 = __fdividef(__int_as_float(pr.w), g_att_sum[pr.z] + 1e-9f);
    pr.y = __float_as_int(a0);
    pr.w = __float_as_int(a1);
    ((int4*)g_edge2)[q] = pr;
}

// ---------------- K5: gather moments, one warp per src node (8-wide) ---------
__global__ __launch_bounds__(128) void k_gather() {
    int s = blockIdx.x * 4 + (threadIdx.x >> 5);
    int lane = threadIdx.x & 31;
    if (s >= NODES) return;

    int start = g_offsets[s];
    int end   = g_offsets[s + 1];

    float4 accx = make_float4(0.f, 0.f, 0.f, 0.f);
    float acce = 0.f;
    float accA = 0.f;

    int i = start;
    for (; i + 8 <= end; i += 8) {
        int2 m[8];
        #pragma unroll
        for (int k = 0; k < 8; k++) m[k] = g_edge2[i + k];
        uint2 r[8];
        #pragma unroll
        for (int k = 0; k < 8; k++)
            r[k] = *(const uint2*)&g_xh[(size_t)m[k].x * Dd + lane * 4];
        float h[8];
        #pragma unroll
        for (int k = 0; k < 8; k++)
            h[k] = __half2float(g_eh[(size_t)(i + k) * DE + lane]);
        #pragma unroll
        for (int k = 0; k < 8; k++) {
            float a = __int_as_float(m[k].y);
            float4 v = h4tof4(r[k]);
            accx.x += a * v.x; accx.y += a * v.y;
            accx.z += a * v.z; accx.w += a * v.w;
            acce += a * h[k];
            accA += a;
        }
    }
    for (; i < end; i++) {
        int2 m = g_edge2[i];
        float h = __half2float(g_eh[(size_t)i * DE + lane]);
        uint2 r = *(const uint2*)&g_xh[(size_t)m.x * Dd + lane * 4];
        float a = __int_as_float(m.y);
        float4 v = h4tof4(r);
        accx.x += a * v.x; accx.y += a * v.y;
        accx.z += a * v.z; accx.w += a * v.w;
        acce += a * h;
        accA += a;
    }

    *(float4*)&g_Mx[(size_t)s * Dd + lane * 4] = accx;
    g_Me[(size_t)s * DE + lane] = acce;
    if (lane == 0) g_sA[s] = accA;
}

// ---------------- K6: tf32 tensor-core epilogue GEMM -------------------------
#define OB_M 128
#define OB_K 16
#define NTILES 10
#define ASTR 20
#define BSTR 136
__global__ __launch_bounds__(256) void k_out(const float* __restrict__ Wv,
                                             const float* __restrict__ Wev,
                                             float* __restrict__ out) {
    __shared__ float As[2][OB_M * ASTR];
    __shared__ float Bs[2][OB_K * BSTR];
    __shared__ float sA_sh[OB_M];
    __shared__ float bb_sh[Dd];

    int t  = threadIdx.x;
    int m0 = blockIdx.x * OB_M;
    if (t < OB_M) {
        sA_sh[t] = g_sA[m0 + t];
        bb_sh[t] = g_bvev[t];
    }

    auto issue = [&](int stage, int tile) {
        #pragma unroll
        for (int it = 0; it < 2; it++) {
            int q = t + it * 256;
            int m = q >> 2, kq = q & 3;
            const float* srcA = (tile < 8)
                ? &g_Mx[(size_t)(m0 + m) * Dd + tile * OB_K + kq * 4]
                : &g_Me[(size_t)(m0 + m) * DE + (tile - 8) * OB_K + kq * 4];
            cp16(&As[stage][m * ASTR + kq * 4], srcA);
            int k = q >> 5, c4 = q & 31;
            const float* srcB = (tile < 8)
                ? &Wv[(size_t)(tile * OB_K + k) * Dd + c4 * 4]
                : &Wev[(size_t)((tile - 8) * OB_K + k) * Dd + c4 * 4];
            cp16(&Bs[stage][k * BSTR + c4 * 4], srcB);
        }
    };

    issue(0, 0);
    CP_COMMIT();

    int wid  = t >> 5;
    int lane = t & 31;
    int warp_m = wid >> 1;
    int warp_n = wid & 1;
    int gID = lane >> 2, tig = lane & 3;

    float d[2][8][4];
    #pragma unroll
    for (int mi = 0; mi < 2; mi++)
        #pragma unroll
        for (int ni = 0; ni < 8; ni++)
            #pragma unroll
            for (int k = 0; k < 4; k++) d[mi][ni][k] = 0.f;

    for (int tile = 0; tile < NTILES; tile++) {
        int cur = tile & 1, nxt = cur ^ 1;
        if (tile + 1 < NTILES) {
            issue(nxt, tile + 1);
            CP_COMMIT();
            CP_WAIT(1);
        } else {
            CP_WAIT(0);
        }
        __syncthreads();
        #pragma unroll
        for (int ks = 0; ks < OB_K; ks += 8) {
            uint32_t a[2][4];
            #pragma unroll
            for (int mi = 0; mi < 2; mi++) {
                int r0 = warp_m * 32 + mi * 16 + gID;
                a[mi][0] = f2tf32(As[cur][(r0)     * ASTR + ks + tig]);
                a[mi][1] = f2tf32(As[cur][(r0 + 8) * ASTR + ks + tig]);
                a[mi][2] = f2tf32(As[cur][(r0)     * ASTR + ks + tig + 4]);
                a[mi][3] = f2tf32(As[cur][(r0 + 8) * ASTR + ks + tig + 4]);
            }
            #pragma unroll
            for (int ni = 0; ni < 8; ni++) {
                int cn = warp_n * 64 + ni * 8 + gID;
                uint32_t b0 = f2tf32(Bs[cur][(ks + tig)     * BSTR + cn]);
                uint32_t b1 = f2tf32(Bs[cur][(ks + tig + 4) * BSTR + cn]);
                mma_tf32(d[0][ni], a[0], b0, b1);
                mma_tf32(d[1][ni], a[1], b0, b1);
            }
        }
        __syncthreads();
    }

    #pragma unroll
    for (int mi = 0; mi < 2; mi++) {
        int rl = warp_m * 32 + mi * 16 + gID;
        int rh = rl + 8;
        int r_lo = m0 + rl, r_hi = m0 + rh;
        float sa_lo = sA_sh[rl], sa_hi = sA_sh[rh];
        #pragma unroll
        for (int ni = 0; ni < 8; ni++) {
            int c = warp_n * 64 + ni * 8 + tig * 2;
            float b0 = bb_sh[c], b1 = bb_sh[c + 1];
            if (r_lo < NODES) {
                float2 o = make_float2(d[mi][ni][0] + sa_lo * b0,
                                       d[mi][ni][1] + sa_lo * b1);
                *(float2*)&out[(size_t)r_lo * Dd + c] = o;
            }
            if (r_hi < NODES) {
                float2 o = make_float2(d[mi][ni][2] + sa_hi * b0,
                                       d[mi][ni][3] + sa_hi * b1);
                *(float2*)&out[(size_t)r_hi * Dd + c] = o;
            }
        }
    }
}

// ---------------- launch ------------------------------------------------------
extern "C" void kernel_launch(void* const* d_in, const int* in_sizes, int n_in,
                              void* d_out, int out_size) {
    const float* x     = (const float*)d_in[0];
    const int*   ei    = (const int*)  d_in[1];
    const float* e_emb = (const float*)d_in[2];
    const int*   bi    = (const int*)  d_in[3];
    const float* Wq    = (const float*)d_in[4];
    const float* bq    = (const float*)d_in[5];
    const float* Wk    = (const float*)d_in[6];
    const float* bk    = (const float*)d_in[7];
    const float* Wv    = (const float*)d_in[8];
    const float* bv    = (const float*)d_in[9];
    const float* Wew   = (const float*)d_in[10];
    const float* bew   = (const float*)d_in[11];
    const float* Wev   = (const float*)d_in[12];
    const float* bev   = (const float*)d_in[13];
    const float* Wa    = (const float*)d_in[14];
    float* out = (float*)d_out;

    k_init<<<ZERO_BLKS + 16, 256>>>(Wq, Wk, Wew, bq, bk, bew, Wa, bv, bev);
    k_fxc<<<FX_BLKS + (Ee / 4 + 255) / 256, 256>>>(x, ei, bi);
    k_scanA<<<SCAN_BLKS, 256>>>();
    k_scanB<<<SCAN_BLKS, 256>>>();
    k_edge1<<<Ee / 256, 256>>>(ei, e_emb, bi);
    k_alpha<<<(Ee / 2 + 255) / 256, 256>>>();
    k_gather<<<(NODES + 3) / 4, 128>>>();
    k_out<<<NODES_PAD / OB_M, 256>>>(Wv, Wev, out);
}